// round 4
// baseline (speedup 1.0000x reference)
#include <cuda_runtime.h>
#include <cuda_fp16.h>
#include <cstdint>

// Problem constants
#define OUT_F   11008
#define IN_F    4096
#define GSZ     128
#define NGROUPS 32
#define M_TOT   8192        // 4 * 2048

// GEMM tiling
#define BM 128
#define BN 128
#define BK 64
#define NTHREADS 256

// Scratch (device globals — allocation-free per harness rules)
__device__ __align__(16) __half g_W16[(size_t)OUT_F * IN_F];   // ~90 MB
__device__ __align__(16) __half g_X16[(size_t)M_TOT * IN_F];   // ~67 MB

// ---------------------------------------------------------------------------
// x fp32 -> fp16
// ---------------------------------------------------------------------------
__global__ void __launch_bounds__(256) xcvt_kernel(const float4* __restrict__ x) {
    int idx = blockIdx.x * 256 + threadIdx.x;      // exact: M_TOT*IN_F/4 threads
    float4 v = x[idx];
    __half2 h0 = __floats2half2_rn(v.x, v.y);
    __half2 h1 = __floats2half2_rn(v.z, v.w);
    uint2 u;
    u.x = reinterpret_cast<uint32_t&>(h0);
    u.y = reinterpret_cast<uint32_t&>(h1);
    *reinterpret_cast<uint2*>(&g_X16[(size_t)idx * 4]) = u;
}

// ---------------------------------------------------------------------------
// int4 dequant -> fp16 weights
// weight_packed: int32 [O, I/2], each element holds one byte (two nibbles).
// even idx = (b & 15) - 8, odd idx = ((b >> 4) & 15) - 8, scaled per group of 128.
// ---------------------------------------------------------------------------
__global__ void __launch_bounds__(256) dequant_kernel(const int4* __restrict__ wp,
                                                      const float* __restrict__ scales) {
    int idx = blockIdx.x * 256 + threadIdx.x;      // exact: OUT_F*(IN_F/2)/4 threads
    int4 p = wp[idx];
    int base = idx * 4;                            // packed-byte index
    int o = base >> 11;                            // / (IN_F/2 = 2048)
    int c = base & 2047;                           // packed col; output col i = 2c
    int g = c >> 6;                                // group = (2c)/128 = c/64 (same for all 8)
    float s = scales[o * NGROUPS + g];
    __align__(16) __half hs[8];
    int v[4] = {p.x, p.y, p.z, p.w};
#pragma unroll
    for (int j = 0; j < 4; j++) {
        int b = v[j] & 0xFF;
        hs[2 * j]     = __float2half_rn((float)((b & 15) - 8) * s);
        hs[2 * j + 1] = __float2half_rn((float)(((b >> 4) & 15) - 8) * s);
    }
    *reinterpret_cast<uint4*>(&g_W16[(size_t)o * IN_F + 2 * c]) = *reinterpret_cast<uint4*>(hs);
}

// ---------------------------------------------------------------------------
// fp16 tensor-core GEMM: out[M,N] = X16[M,K] @ W16[N,K]^T, fp32 accumulate
// ---------------------------------------------------------------------------
__device__ __forceinline__ void ldsm4(uint32_t* r, uint32_t addr) {
    asm volatile("ldmatrix.sync.aligned.m8n8.x4.shared.b16 {%0,%1,%2,%3}, [%4];\n"
                 : "=r"(r[0]), "=r"(r[1]), "=r"(r[2]), "=r"(r[3]) : "r"(addr));
}

__device__ __forceinline__ void mma16816(float* d, const uint32_t* a, const uint32_t* b) {
    asm volatile(
        "mma.sync.aligned.m16n8k16.row.col.f32.f16.f16.f32 "
        "{%0,%1,%2,%3}, {%4,%5,%6,%7}, {%8,%9}, {%0,%1,%2,%3};\n"
        : "+f"(d[0]), "+f"(d[1]), "+f"(d[2]), "+f"(d[3])
        : "r"(a[0]), "r"(a[1]), "r"(a[2]), "r"(a[3]), "r"(b[0]), "r"(b[1]));
}

__device__ __forceinline__ void cpa16(uint32_t dst, const void* src) {
    asm volatile("cp.async.cg.shared.global [%0], [%1], 16;\n" :: "r"(dst), "l"(src));
}

extern __shared__ __align__(16) __half smem_buf[];

__global__ void __launch_bounds__(NTHREADS) gemm_kernel(float* __restrict__ out) {
    const int tid  = threadIdx.x;
    const int lane = tid & 31;
    const int wid  = tid >> 5;
    const int warp_m = wid & 1;   // 2 warp rows  (64 M each)
    const int warp_n = wid >> 1;  // 4 warp cols  (32 N each)
    const int m0 = blockIdx.x * BM;
    const int n0 = blockIdx.y * BN;

    uint32_t s_base = (uint32_t)__cvta_generic_to_shared(smem_buf);
    // halves layout: As[0], As[1], Bs[0], Bs[1]  (each BM*BK = 8192 halves)
    const uint32_t A_off[2] = { s_base,                 s_base + BM * BK * 2 };
    const uint32_t B_off[2] = { s_base + 2 * BM * BK * 2, s_base + (2 * BM * BK + BN * BK) * 2 };

    float acc[4][4][4];
#pragma unroll
    for (int i = 0; i < 4; i++)
#pragma unroll
        for (int j = 0; j < 4; j++)
#pragma unroll
            for (int k = 0; k < 4; k++) acc[i][j][k] = 0.0f;

    const __half* gA = g_X16 + (size_t)m0 * IN_F;
    const __half* gB = g_W16 + (size_t)n0 * IN_F;

    // SW128-style swizzle: 8 chunks (16B) per 128B row, phys chunk = c ^ (row & 7)
    // --- preload tile 0 ---
    {
#pragma unroll
        for (int j = 0; j < 4; j++) {
            int cid = tid + j * NTHREADS;
            int r = cid >> 3, c = cid & 7;
            cpa16(A_off[0] + (r * BK + ((c ^ (r & 7)) << 3)) * 2, gA + (size_t)r * IN_F + c * 8);
        }
#pragma unroll
        for (int j = 0; j < 4; j++) {
            int cid = tid + j * NTHREADS;
            int r = cid >> 3, c = cid & 7;
            cpa16(B_off[0] + (r * BK + ((c ^ (r & 7)) << 3)) * 2, gB + (size_t)r * IN_F + c * 8);
        }
        asm volatile("cp.async.commit_group;\n" ::: "memory");
    }

    const int NKT = IN_F / BK;   // 64
    for (int kt = 0; kt < NKT; kt++) {
        asm volatile("cp.async.wait_group 0;\n" ::: "memory");
        __syncthreads();

        if (kt + 1 < NKT) {
            int b = (kt + 1) & 1;
            const __half* gA2 = gA + (kt + 1) * BK;
            const __half* gB2 = gB + (kt + 1) * BK;
#pragma unroll
            for (int j = 0; j < 4; j++) {
                int cid = tid + j * NTHREADS;
                int r = cid >> 3, c = cid & 7;
                cpa16(A_off[b] + (r * BK + ((c ^ (r & 7)) << 3)) * 2, gA2 + (size_t)r * IN_F + c * 8);
            }
#pragma unroll
            for (int j = 0; j < 4; j++) {
                int cid = tid + j * NTHREADS;
                int r = cid >> 3, c = cid & 7;
                cpa16(B_off[b] + (r * BK + ((c ^ (r & 7)) << 3)) * 2, gB2 + (size_t)r * IN_F + c * 8);
            }
            asm volatile("cp.async.commit_group;\n" ::: "memory");
        }

        const int b = kt & 1;
        const int mat = lane >> 3, rr = lane & 7;
#pragma unroll
        for (int ks = 0; ks < 4; ks++) {           // 4 x k16 per BK=64 tile
            uint32_t afr[4][4];
            uint32_t bfr[4][2];
#pragma unroll
            for (int mi = 0; mi < 4; mi++) {
                int row = warp_m * 64 + mi * 16 + (mat & 1) * 8 + rr;
                int ch  = ks * 2 + (mat >> 1);
                ldsm4(afr[mi], A_off[b] + (row * BK + ((ch ^ (row & 7)) << 3)) * 2);
            }
#pragma unroll
            for (int np = 0; np < 2; np++) {
                int nrow = warp_n * 32 + np * 16 + ((mat >> 1) << 3) + rr;
                int ch   = ks * 2 + (mat & 1);
                uint32_t t4[4];
                ldsm4(t4, B_off[b] + (nrow * BK + ((ch ^ (nrow & 7)) << 3)) * 2);
                bfr[2 * np][0] = t4[0]; bfr[2 * np][1] = t4[1];
                bfr[2 * np + 1][0] = t4[2]; bfr[2 * np + 1][1] = t4[3];
            }
#pragma unroll
            for (int mi = 0; mi < 4; mi++)
#pragma unroll
                for (int ni = 0; ni < 4; ni++)
                    mma16816(acc[mi][ni], afr[mi], bfr[ni]);
        }
        __syncthreads();
    }

    // epilogue: fp32 output, full coverage (no tails anywhere)
#pragma unroll
    for (int mi = 0; mi < 4; mi++) {
        int row = m0 + warp_m * 64 + mi * 16 + (lane >> 2);
#pragma unroll
        for (int ni = 0; ni < 4; ni++) {
            int col = n0 + warp_n * 32 + ni * 8 + (lane & 3) * 2;
            float2 v0 = make_float2(acc[mi][ni][0], acc[mi][ni][1]);
            float2 v1 = make_float2(acc[mi][ni][2], acc[mi][ni][3]);
            *reinterpret_cast<float2*>(&out[(size_t)row * OUT_F + col]) = v0;
            *reinterpret_cast<float2*>(&out[(size_t)(row + 8) * OUT_F + col]) = v1;
        }
    }
}

// ---------------------------------------------------------------------------
// Launch
// ---------------------------------------------------------------------------
extern "C" void kernel_launch(void* const* d_in, const int* in_sizes, int n_in,
                              void* d_out, int out_size) {
    const float* x      = (const float*)d_in[0];   // [4,2048,4096] fp32
    const int*   wp     = (const int*)d_in[1];     // [11008,2048] int32 (bytes)
    const float* scales = (const float*)d_in[2];   // [11008,32] fp32
    float* out = (float*)d_out;                    // [4,2048,11008] fp32

    // prep: x -> fp16, W -> dequant fp16
    xcvt_kernel<<<(M_TOT * IN_F / 4) / 256, 256>>>((const float4*)x);
    dequant_kernel<<<(OUT_F * (IN_F / 2) / 4) / 256, 256>>>((const int4*)wp, scales);

    // GEMM
    const int smem_bytes = 2 * (BM * BK + BN * BK) * (int)sizeof(__half);  // 64 KB
    cudaFuncSetAttribute(gemm_kernel, cudaFuncAttributeMaxDynamicSharedMemorySize, smem_bytes);
    dim3 grid(M_TOT / BM, OUT_F / BN);   // (64, 86); m fastest -> B strip L2 reuse
    gemm_kernel<<<grid, NTHREADS, smem_bytes>>>(out);
}

// round 7
// speedup vs baseline: 2.8264x; 2.8264x over previous
#include <cuda_runtime.h>
#include <cuda.h>
#include <cuda_fp16.h>
#include <cstdint>

// Problem constants
#define OUT_F   11008
#define IN_F    4096
#define NGROUPS 32
#define M_TOT   8192        // 4 * 2048

// ---------------------------------------------------------------------------
// Arch-feature detection: tcgen05 is sm_103a-(arch/family)-specific.
// In the plain compute_103/sm_103 pass these macros are undefined and the
// tcgen05 kernel compiles to an empty body; the mma.sync fallback kernel
// compiles to an empty body in the arch-specific pass. Both are always
// launched; exactly one does the work in whichever image the runtime loads.
// ---------------------------------------------------------------------------
#if defined(__CUDA_ARCH__) && (defined(__CUDA_ARCH_FEAT_SM103_ALL) || \
                               defined(__CUDA_ARCH_FEAT_SM100_ALL) || \
                               defined(__CUDA_ARCH_SPECIFIC__)     || \
                               defined(__CUDA_ARCH_FAMILY_SPECIFIC__))
#define HAS_TCGEN05 1
#else
#define HAS_TCGEN05 0
#endif

// Scratch (device globals — allocation-free per harness rules)
__device__ __align__(16) __half g_W16[(size_t)OUT_F * IN_F];   // ~90 MB
__device__ __align__(16) __half g_X16[(size_t)M_TOT * IN_F];   // ~67 MB

// ---------------------------------------------------------------------------
// x fp32 -> fp16
// ---------------------------------------------------------------------------
__global__ void __launch_bounds__(256) xcvt_kernel(const float4* __restrict__ x) {
    int idx = blockIdx.x * 256 + threadIdx.x;      // exact: M_TOT*IN_F/4 threads
    float4 v = x[idx];
    __half2 h0 = __floats2half2_rn(v.x, v.y);
    __half2 h1 = __floats2half2_rn(v.z, v.w);
    uint2 u;
    u.x = reinterpret_cast<uint32_t&>(h0);
    u.y = reinterpret_cast<uint32_t&>(h1);
    *reinterpret_cast<uint2*>(&g_X16[(size_t)idx * 4]) = u;
}

// ---------------------------------------------------------------------------
// int4 dequant -> fp16 weights
// ---------------------------------------------------------------------------
__global__ void __launch_bounds__(256) dequant_kernel(const int4* __restrict__ wp,
                                                      const float* __restrict__ scales) {
    int idx = blockIdx.x * 256 + threadIdx.x;      // exact: OUT_F*(IN_F/2)/4 threads
    int4 p = wp[idx];
    int base = idx * 4;                            // packed-byte index
    int o = base >> 11;                            // / (IN_F/2 = 2048)
    int c = base & 2047;                           // packed col; output col i = 2c
    int g = c >> 6;                                // group = c/64 (same for all 8 outputs)
    float s = scales[o * NGROUPS + g];
    __align__(16) __half hs[8];
    int v[4] = {p.x, p.y, p.z, p.w};
#pragma unroll
    for (int j = 0; j < 4; j++) {
        int b = v[j] & 0xFF;
        hs[2 * j]     = __float2half_rn((float)((b & 15) - 8) * s);
        hs[2 * j + 1] = __float2half_rn((float)(((b >> 4) & 15) - 8) * s);
    }
    *reinterpret_cast<uint4*>(&g_W16[(size_t)o * IN_F + 2 * c]) = *reinterpret_cast<uint4*>(hs);
}

// ===========================================================================
// Path A: tcgen05 GEMM (sm_103a pass only)
// out[M,N] = X16[M,K] @ W16[N,K]^T, f32 accum in TMEM
// ===========================================================================
#define BM 128
#define BN 256
#define BK 64               // halves per stage (128 B rows -> SW128)
#define NSTAGE 4
#define KTILES (IN_F / BK)  // 64
#define GEMM_THREADS 192    // warps 0-3 epilogue, warp 4 TMA, warp 5 MMA

// SMEM byte offsets
#define SM_TMEMPTR  0
#define SM_FULL(s)  (16 + (s) * 8)
#define SM_EMPTY(s) (48 + (s) * 8)
#define SM_DONE     80
#define SM_A(s)     (1024 + (s) * (BM * BK * 2))                          // 16 KB each
#define SM_B(s)     (1024 + NSTAGE * (BM * BK * 2) + (s) * (BN * BK * 2)) // 32 KB each
#define SMEM_TOTAL  (1024 + NSTAGE * (BM * BK + BN * BK) * 2)             // 197632 B
#define STAGE_BYTES ((BM + BN) * BK * 2)                                  // 49152

// idesc: kind::f16, A/B fp16 (0), D f32, M=128, N=128 (two MMAs cover BN=256)
#define IDESC 0x8200010u

#if HAS_TCGEN05
// SW128 K-major SMEM descriptor base: layout=SW128(2), version=1, SBO=64, LBO=1
#define DESC_BASE ((2ull << 61) | (1ull << 46) | (64ull << 32) | (1ull << 16))
__device__ __forceinline__ uint64_t make_desc(uint32_t addr) {
    return DESC_BASE | ((uint64_t)(addr >> 4) & 0x3FFFull);
}
__device__ __forceinline__ void mbar_init(uint32_t a, uint32_t cnt) {
    asm volatile("mbarrier.init.shared::cta.b64 [%0], %1;" :: "r"(a), "r"(cnt) : "memory");
}
__device__ __forceinline__ void mbar_expect_tx(uint32_t a, uint32_t bytes) {
    asm volatile("mbarrier.arrive.expect_tx.shared::cta.b64 _, [%0], %1;"
                 :: "r"(a), "r"(bytes) : "memory");
}
__device__ __forceinline__ void mbar_wait(uint32_t a, uint32_t parity) {
    asm volatile(
        "{\n\t.reg .pred P;\n\t"
        "W_%=:\n\t"
        "mbarrier.try_wait.parity.shared::cta.b64 P, [%0], %1, 0x989680;\n\t"
        "@P bra.uni D_%=;\n\t"
        "bra.uni W_%=;\n\t"
        "D_%=:\n\t}"
        :: "r"(a), "r"(parity) : "memory");
}
__device__ __forceinline__ void tma_2d(uint32_t dst, const CUtensorMap* m,
                                       int x, int y, uint32_t mbar) {
    asm volatile(
        "cp.async.bulk.tensor.2d.shared::cta.global.tile.mbarrier::complete_tx::bytes "
        "[%0], [%1, {%2, %3}], [%4];"
        :: "r"(dst), "l"(m), "r"(x), "r"(y), "r"(mbar) : "memory");
}
__device__ __forceinline__ void mma_f16_ss(uint32_t d, uint64_t ad, uint64_t bd,
                                           uint32_t en) {
    asm volatile(
        "{\n\t.reg .pred p;\n\t"
        "setp.ne.u32 p, %4, 0;\n\t"
        "tcgen05.mma.cta_group::1.kind::f16 [%0], %1, %2, %3, {%5, %5, %5, %5}, p;\n\t}"
        :: "r"(d), "l"(ad), "l"(bd), "r"(IDESC), "r"(en), "r"(0u) : "memory");
}
__device__ __forceinline__ void tc_commit(uint32_t mbar) {
    asm volatile(
        "tcgen05.commit.cta_group::1.mbarrier::arrive::one.shared::cluster.b64 [%0];"
        :: "r"(mbar) : "memory");
}
#endif  // HAS_TCGEN05

__global__ void __launch_bounds__(GEMM_THREADS)
gemm_tc_kernel(const __grid_constant__ CUtensorMap tmA,
               const __grid_constant__ CUtensorMap tmB,
               float* __restrict__ out) {
#if HAS_TCGEN05
    extern __shared__ __align__(1024) char smem[];
    uint32_t sbase = (uint32_t)__cvta_generic_to_shared(smem);
    const int tid = threadIdx.x;
    const int wid = tid >> 5;
    const int lane = tid & 31;
    const int m0 = blockIdx.x * BM;
    const int n0 = blockIdx.y * BN;

    if (tid == 0) {
#pragma unroll
        for (int s = 0; s < NSTAGE; s++) {
            mbar_init(sbase + SM_FULL(s), 1);
            mbar_init(sbase + SM_EMPTY(s), 1);
        }
        mbar_init(sbase + SM_DONE, 1);
    }
    if (wid == 5) {  // warp-collective TMEM alloc: 256 f32 cols for D
        asm volatile("tcgen05.alloc.cta_group::1.sync.aligned.shared::cta.b32 [%0], %1;"
                     :: "r"(sbase + SM_TMEMPTR), "r"(256u) : "memory");
        asm volatile("tcgen05.relinquish_alloc_permit.cta_group::1.sync.aligned;");
    }
    __syncthreads();
    uint32_t tmem;
    asm volatile("ld.shared.b32 %0, [%1];" : "=r"(tmem) : "r"(sbase + SM_TMEMPTR));

    if (wid == 4 && lane == 0) {
        // ---- TMA producer ----
        int phase = 1;  // first empty-wait passes immediately
        for (int kt = 0; kt < KTILES; kt++) {
            int st = kt & (NSTAGE - 1);
            mbar_wait(sbase + SM_EMPTY(st), (uint32_t)phase);
            if (st == NSTAGE - 1) phase ^= 1;
            mbar_expect_tx(sbase + SM_FULL(st), STAGE_BYTES);
            tma_2d(sbase + SM_A(st), &tmA, kt * BK, m0, sbase + SM_FULL(st));
            tma_2d(sbase + SM_B(st), &tmB, kt * BK, n0, sbase + SM_FULL(st));
        }
    } else if (wid == 5 && lane == 0) {
        // ---- MMA issuer ----
        int phase = 0;
        for (int kt = 0; kt < KTILES; kt++) {
            int st = kt & (NSTAGE - 1);
            mbar_wait(sbase + SM_FULL(st), (uint32_t)phase);
            if (st == NSTAGE - 1) phase ^= 1;
            uint64_t ad  = make_desc(sbase + SM_A(st));
            uint64_t bd0 = make_desc(sbase + SM_B(st));
            uint64_t bd1 = bd0 + 1024;  // +16 KB = B rows 128..255
#pragma unroll
            for (int ks = 0; ks < 4; ks++) {   // 4 x k16 per BK=64 stage
                uint32_t en = (kt | ks) ? 1u : 0u;
                mma_f16_ss(tmem,       ad + 2 * ks, bd0 + 2 * ks, en);
                mma_f16_ss(tmem + 128, ad + 2 * ks, bd1 + 2 * ks, en);
            }
            tc_commit(sbase + SM_EMPTY(st));   // stage reusable once MMAs drained
        }
        tc_commit(sbase + SM_DONE);            // fires when ALL MMAs complete
    } else if (wid < 4) {
        // ---- epilogue: wait for all MMAs, read TMEM, store f32 ----
        mbar_wait(sbase + SM_DONE, 0);
        asm volatile("tcgen05.fence::after_thread_sync;" ::: "memory");
        int row = m0 + wid * 32 + lane;        // each warp reads its subpartition
        float* orow = out + (size_t)row * OUT_F + n0;
#pragma unroll
        for (int ch = 0; ch < 8; ch++) {       // 8 x 32 cols = 256
            uint32_t r[32];
            asm volatile(
                "tcgen05.ld.sync.aligned.32x32b.x32.b32 "
                "{%0, %1, %2, %3, %4, %5, %6, %7, "
                " %8, %9, %10, %11, %12, %13, %14, %15, "
                " %16, %17, %18, %19, %20, %21, %22, %23, "
                " %24, %25, %26, %27, %28, %29, %30, %31}, [%32];"
                : "=r"(r[0]),  "=r"(r[1]),  "=r"(r[2]),  "=r"(r[3]),
                  "=r"(r[4]),  "=r"(r[5]),  "=r"(r[6]),  "=r"(r[7]),
                  "=r"(r[8]),  "=r"(r[9]),  "=r"(r[10]), "=r"(r[11]),
                  "=r"(r[12]), "=r"(r[13]), "=r"(r[14]), "=r"(r[15]),
                  "=r"(r[16]), "=r"(r[17]), "=r"(r[18]), "=r"(r[19]),
                  "=r"(r[20]), "=r"(r[21]), "=r"(r[22]), "=r"(r[23]),
                  "=r"(r[24]), "=r"(r[25]), "=r"(r[26]), "=r"(r[27]),
                  "=r"(r[28]), "=r"(r[29]), "=r"(r[30]), "=r"(r[31])
                : "r"(tmem + ch * 32));
            asm volatile("tcgen05.wait::ld.sync.aligned;" ::: "memory");
#pragma unroll
            for (int j = 0; j < 8; j++) {
                float4 v = make_float4(__uint_as_float(r[4 * j]),
                                       __uint_as_float(r[4 * j + 1]),
                                       __uint_as_float(r[4 * j + 2]),
                                       __uint_as_float(r[4 * j + 3]));
                *reinterpret_cast<float4*>(orow + ch * 32 + 4 * j) = v;
            }
        }
        asm volatile("tcgen05.fence::before_thread_sync;" ::: "memory");
    }

    __syncthreads();
    if (wid == 5) {  // warp-collective dealloc
        asm volatile("tcgen05.dealloc.cta_group::1.sync.aligned.b32 %0, %1;"
                     :: "r"(tmem), "r"(256u));
    }
#endif  // HAS_TCGEN05
}

// ===========================================================================
// Path B: mma.sync fallback (compiled only in the NON-arch-specific pass)
// Proven round-4 kernel: 128x128x64 tiles, 8 warps, cp.async double buffer.
// ===========================================================================
#define FBM 128
#define FBN 128
#define FBK 64
#define FB_THREADS 256

#if !HAS_TCGEN05
__device__ __forceinline__ void ldsm4(uint32_t* r, uint32_t addr) {
    asm volatile("ldmatrix.sync.aligned.m8n8.x4.shared.b16 {%0,%1,%2,%3}, [%4];\n"
                 : "=r"(r[0]), "=r"(r[1]), "=r"(r[2]), "=r"(r[3]) : "r"(addr));
}
__device__ __forceinline__ void mma16816(float* d, const uint32_t* a, const uint32_t* b) {
    asm volatile(
        "mma.sync.aligned.m16n8k16.row.col.f32.f16.f16.f32 "
        "{%0,%1,%2,%3}, {%4,%5,%6,%7}, {%8,%9}, {%0,%1,%2,%3};\n"
        : "+f"(d[0]), "+f"(d[1]), "+f"(d[2]), "+f"(d[3])
        : "r"(a[0]), "r"(a[1]), "r"(a[2]), "r"(a[3]), "r"(b[0]), "r"(b[1]));
}
__device__ __forceinline__ void cpa16(uint32_t dst, const void* src) {
    asm volatile("cp.async.cg.shared.global [%0], [%1], 16;\n" :: "r"(dst), "l"(src));
}
#endif  // !HAS_TCGEN05

extern __shared__ __align__(16) __half smem_buf[];

__global__ void __launch_bounds__(FB_THREADS) gemm_fb_kernel(float* __restrict__ out) {
#if !HAS_TCGEN05
    const int tid  = threadIdx.x;
    const int lane = tid & 31;
    const int wid  = tid >> 5;
    const int warp_m = wid & 1;   // 2 warp rows  (64 M each)
    const int warp_n = wid >> 1;  // 4 warp cols  (32 N each)
    const int m0 = blockIdx.x * FBM;
    const int n0 = blockIdx.y * FBN;

    uint32_t s_base = (uint32_t)__cvta_generic_to_shared(smem_buf);
    const uint32_t A_off[2] = { s_base,                    s_base + FBM * FBK * 2 };
    const uint32_t B_off[2] = { s_base + 2 * FBM * FBK * 2,
                                s_base + (2 * FBM * FBK + FBN * FBK) * 2 };

    float acc[4][4][4];
#pragma unroll
    for (int i = 0; i < 4; i++)
#pragma unroll
        for (int j = 0; j < 4; j++)
#pragma unroll
            for (int k = 0; k < 4; k++) acc[i][j][k] = 0.0f;

    const __half* gA = g_X16 + (size_t)m0 * IN_F;
    const __half* gB = g_W16 + (size_t)n0 * IN_F;

    {
#pragma unroll
        for (int j = 0; j < 4; j++) {
            int cid = tid + j * FB_THREADS;
            int r = cid >> 3, c = cid & 7;
            cpa16(A_off[0] + (r * FBK + ((c ^ (r & 7)) << 3)) * 2, gA + (size_t)r * IN_F + c * 8);
        }
#pragma unroll
        for (int j = 0; j < 4; j++) {
            int cid = tid + j * FB_THREADS;
            int r = cid >> 3, c = cid & 7;
            cpa16(B_off[0] + (r * FBK + ((c ^ (r & 7)) << 3)) * 2, gB + (size_t)r * IN_F + c * 8);
        }
        asm volatile("cp.async.commit_group;\n" ::: "memory");
    }

    const int NKT = IN_F / FBK;   // 64
    for (int kt = 0; kt < NKT; kt++) {
        asm volatile("cp.async.wait_group 0;\n" ::: "memory");
        __syncthreads();

        if (kt + 1 < NKT) {
            int b = (kt + 1) & 1;
            const __half* gA2 = gA + (kt + 1) * FBK;
            const __half* gB2 = gB + (kt + 1) * FBK;
#pragma unroll
            for (int j = 0; j < 4; j++) {
                int cid = tid + j * FB_THREADS;
                int r = cid >> 3, c = cid & 7;
                cpa16(A_off[b] + (r * FBK + ((c ^ (r & 7)) << 3)) * 2, gA2 + (size_t)r * IN_F + c * 8);
            }
#pragma unroll
            for (int j = 0; j < 4; j++) {
                int cid = tid + j * FB_THREADS;
                int r = cid >> 3, c = cid & 7;
                cpa16(B_off[b] + (r * FBK + ((c ^ (r & 7)) << 3)) * 2, gB2 + (size_t)r * IN_F + c * 8);
            }
            asm volatile("cp.async.commit_group;\n" ::: "memory");
        }

        const int b = kt & 1;
        const int mat = lane >> 3, rr = lane & 7;
#pragma unroll
        for (int ks = 0; ks < 4; ks++) {
            uint32_t afr[4][4];
            uint32_t bfr[4][2];
#pragma unroll
            for (int mi = 0; mi < 4; mi++) {
                int row = warp_m * 64 + mi * 16 + (mat & 1) * 8 + rr;
                int ch  = ks * 2 + (mat >> 1);
                ldsm4(afr[mi], A_off[b] + (row * FBK + ((ch ^ (row & 7)) << 3)) * 2);
            }
#pragma unroll
            for (int np = 0; np < 2; np++) {
                int nrow = warp_n * 32 + np * 16 + ((mat >> 1) << 3) + rr;
                int ch   = ks * 2 + (mat & 1);
                uint32_t t4[4];
                ldsm4(t4, B_off[b] + (nrow * FBK + ((ch ^ (nrow & 7)) << 3)) * 2);
                bfr[2 * np][0] = t4[0]; bfr[2 * np][1] = t4[1];
                bfr[2 * np + 1][0] = t4[2]; bfr[2 * np + 1][1] = t4[3];
            }
#pragma unroll
            for (int mi = 0; mi < 4; mi++)
#pragma unroll
                for (int ni = 0; ni < 4; ni++)
                    mma16816(acc[mi][ni], afr[mi], bfr[ni]);
        }
        __syncthreads();
    }

#pragma unroll
    for (int mi = 0; mi < 4; mi++) {
        int row = m0 + warp_m * 64 + mi * 16 + (lane >> 2);
#pragma unroll
        for (int ni = 0; ni < 4; ni++) {
            int col = n0 + warp_n * 32 + ni * 8 + (lane & 3) * 2;
            float2 v0 = make_float2(acc[mi][ni][0], acc[mi][ni][1]);
            float2 v1 = make_float2(acc[mi][ni][2], acc[mi][ni][3]);
            *reinterpret_cast<float2*>(&out[(size_t)row * OUT_F + col]) = v0;
            *reinterpret_cast<float2*>(&out[(size_t)(row + 8) * OUT_F + col]) = v1;
        }
    }
#endif  // !HAS_TCGEN05
}

// ---------------------------------------------------------------------------
// Launch
// ---------------------------------------------------------------------------
typedef CUresult (CUDAAPI *PFN_encodeTiled_local)(
    CUtensorMap*, CUtensorMapDataType, cuuint32_t, void*,
    const cuuint64_t*, const cuuint64_t*, const cuuint32_t*, const cuuint32_t*,
    CUtensorMapInterleave, CUtensorMapSwizzle, CUtensorMapL2promotion,
    CUtensorMapFloatOOBfill);

extern "C" void kernel_launch(void* const* d_in, const int* in_sizes, int n_in,
                              void* d_out, int out_size) {
    const float* x      = (const float*)d_in[0];   // [4,2048,4096] fp32
    const int*   wp     = (const int*)d_in[1];     // [11008,2048] int32 (bytes)
    const float* scales = (const float*)d_in[2];   // [11008,32] fp32
    float* out = (float*)d_out;                    // [4,2048,11008] fp32

    // prep: x -> fp16, W -> dequant fp16
    xcvt_kernel<<<(M_TOT * IN_F / 4) / 256, 256>>>((const float4*)x);
    dequant_kernel<<<(OUT_F * (IN_F / 2) / 4) / 256, 256>>>((const int4*)wp, scales);

    // tensormaps (driver entry point via runtime — no -lcuda link dependency)
    PFN_encodeTiled_local encode = nullptr;
    cudaDriverEntryPointQueryResult qres;
    cudaGetDriverEntryPoint("cuTensorMapEncodeTiled", (void**)&encode,
                            cudaEnableDefault, &qres);
    void *pX = nullptr, *pW = nullptr;
    cudaGetSymbolAddress(&pX, g_X16);
    cudaGetSymbolAddress(&pW, g_W16);

    CUtensorMap tmA, tmB;
    if (encode) {
        cuuint64_t dimsA[2]  = {IN_F, M_TOT};
        cuuint64_t strA[1]   = {IN_F * 2};
        cuuint32_t boxA[2]   = {BK, BM};           // 64 halves (=128B, SW128) x 128 rows
        cuuint32_t es[2]     = {1, 1};
        encode(&tmA, CU_TENSOR_MAP_DATA_TYPE_FLOAT16, 2, pX, dimsA, strA, boxA, es,
               CU_TENSOR_MAP_INTERLEAVE_NONE, CU_TENSOR_MAP_SWIZZLE_128B,
               CU_TENSOR_MAP_L2_PROMOTION_L2_128B, CU_TENSOR_MAP_FLOAT_OOB_FILL_NONE);
        cuuint64_t dimsB[2]  = {IN_F, OUT_F};
        cuuint64_t strB[1]   = {IN_F * 2};
        cuuint32_t boxB[2]   = {BK, BN};           // 64 halves x 256 rows
        encode(&tmB, CU_TENSOR_MAP_DATA_TYPE_FLOAT16, 2, pW, dimsB, strB, boxB, es,
               CU_TENSOR_MAP_INTERLEAVE_NONE, CU_TENSOR_MAP_SWIZZLE_128B,
               CU_TENSOR_MAP_L2_PROMOTION_L2_128B, CU_TENSOR_MAP_FLOAT_OOB_FILL_NONE);
    }

    // Path A: tcgen05 (no-op body if the loaded image is the non-"a" pass)
    cudaFuncSetAttribute(gemm_tc_kernel, cudaFuncAttributeMaxDynamicSharedMemorySize,
                         SMEM_TOTAL);
    dim3 gridA(M_TOT / BM, OUT_F / BN);   // (64, 43)
    gemm_tc_kernel<<<gridA, GEMM_THREADS, SMEM_TOTAL>>>(tmA, tmB, out);

    // Path B: mma.sync fallback (no-op body in the sm_103a image)
    const int fb_smem = 2 * (FBM * FBK + FBN * FBK) * (int)sizeof(__half);  // 64 KB
    cudaFuncSetAttribute(gemm_fb_kernel, cudaFuncAttributeMaxDynamicSharedMemorySize,
                         fb_smem);
    dim3 gridB(M_TOT / FBM, OUT_F / FBN); // (64, 86)
    gemm_fb_kernel<<<gridB, FB_THREADS, fb_smem>>>(out);
}